// round 12
// baseline (speedup 1.0000x reference)
#include <cuda_runtime.h>
#include <math.h>

#define GAMMA_F 0.99f
#define TAU 64          // tau == tauP == 64
#define WPB 8           // warps (= batch elements) per block
#define THREADS (WPB * 32)

// Barrier-free design: each WARP owns one batch element b end-to-end.
// lane -> taus {lane, lane+32}; gathered values stay in registers; targets
// are exchanged via shfl broadcast (no smem staging, no phase barrier).
// Warps run fully independently -> gather latency of one warp is covered by
// compute of others (no chip-wide phase locking).
__global__ void __launch_bounds__(THREADS)
iqn_td_fused_kernel(const float* __restrict__ q,          // (tau, B, N)
                    const float* __restrict__ next_n_q,   // (tauP, B, N)
                    const int*   __restrict__ action,     // (B,)
                    const int*   __restrict__ next_action,// (B,)
                    const float* __restrict__ reward,     // (T, B)
                    const int*   __restrict__ done,       // (B,)
                    const float* __restrict__ replay_q,   // (tau, B)
                    const float* __restrict__ weight,     // (B,)
                    float* __restrict__ out,              // out[0]=loss, out[1..B]=td
                    int B, int N, int T, float gamma_T)
{
    const int tid  = threadIdx.x;
    const int lane = tid & 31;
    const int w    = tid >> 5;                  // warp -> b
    const int b    = blockIdx.x * WPB + w;

    __shared__ float s_wsum[WPB];

    // ---- per-b scalars (uniform across warp: broadcast loads) ----
    const int   a    = action[b];
    const int   an   = next_action[b];
    float r_sum = 0.0f, g = 1.0f;
    #pragma unroll 4
    for (int tt = 0; tt < T; ++tt) {
        r_sum = fmaf(g, reward[tt * B + b], r_sum);
        g *= GAMMA_F;
    }
    const float coef = (done[b] != 0) ? 0.0f : gamma_T;

    // ---- gathers: 4 independent LDGs, results stay in registers ----
    const size_t plane = (size_t)B * (size_t)N;
    const size_t rowb  = (size_t)b * (size_t)N;
    const int t0 = lane, t1 = lane + 32;

    const float qsa0 = q[(size_t)t0 * plane + rowb + a];
    const float qsa1 = q[(size_t)t1 * plane + rowb + a];
    const float tn0  = next_n_q[(size_t)t0 * plane + rowb + an];
    const float tn1  = next_n_q[(size_t)t1 * plane + rowb + an];

    const float rq0  = replay_q[t0 * B + b];
    const float rq1  = replay_q[t1 * B + b];
    const float rq0m = 1.0f - rq0;
    const float rq1m = 1.0f - rq1;

    const float tgt0 = fmaf(coef, tn0, r_sum);  // targets for tp = lane
    const float tgt1 = fmaf(coef, tn1, r_sum);  // targets for tp = lane+32

    // ---- pair loop: broadcast each target to all lanes via shfl ----
    // kappa=1: c = min(|u|,1); h = c*(0.5c-1)+|u|; f = (u<0) ? (1-rq) : rq
    float acc0 = 0.0f, acc1 = 0.0f;
    #pragma unroll 8
    for (int j = 0; j < 32; ++j) {
        const float ta = __shfl_sync(0xffffffffu, tgt0, j);
        const float tb = __shfl_sync(0xffffffffu, tgt1, j);
        {   const float u = ta - qsa0, au = fabsf(u), c = fminf(au, 1.0f);
            acc0 = fmaf((u < 0.0f) ? rq0m : rq0, fmaf(c, fmaf(0.5f, c, -1.0f), au), acc0); }
        {   const float u = ta - qsa1, au = fabsf(u), c = fminf(au, 1.0f);
            acc1 = fmaf((u < 0.0f) ? rq1m : rq1, fmaf(c, fmaf(0.5f, c, -1.0f), au), acc1); }
        {   const float u = tb - qsa0, au = fabsf(u), c = fminf(au, 1.0f);
            acc0 = fmaf((u < 0.0f) ? rq0m : rq0, fmaf(c, fmaf(0.5f, c, -1.0f), au), acc0); }
        {   const float u = tb - qsa1, au = fabsf(u), c = fminf(au, 1.0f);
            acc1 = fmaf((u < 0.0f) ? rq1m : rq1, fmaf(c, fmaf(0.5f, c, -1.0f), au), acc1); }
    }

    // ---- warp reduce: sum over all (tau, tp) pairs of this b ----
    float tot = acc0 + acc1;
    #pragma unroll
    for (int off = 16; off > 0; off >>= 1)
        tot += __shfl_down_sync(0xffffffffu, tot, off);

    if (lane == 0) {
        const float td = tot * (1.0f / (float)TAU);   // mean over tauP
        out[1 + b] = td;
        s_wsum[w] = td * weight[b];
    }
    __syncthreads();                                   // only barrier in kernel

    // ---- one atomic per CTA ----
    if (tid < WPB) {
        float v = s_wsum[tid];
        #pragma unroll
        for (int off = WPB / 2; off > 0; off >>= 1)
            v += __shfl_down_sync((1u << WPB) - 1u, v, off);
        if (tid == 0)
            atomicAdd(out, v * (1.0f / (float)B));
    }
}

extern "C" void kernel_launch(void* const* d_in, const int* in_sizes, int n_in,
                              void* d_out, int out_size)
{
    const float* q        = (const float*)d_in[0];
    const float* next_n_q = (const float*)d_in[1];
    const int*   action   = (const int*)  d_in[2];
    const int*   naction  = (const int*)  d_in[3];
    const float* reward   = (const float*)d_in[4];
    const int*   done     = (const int*)  d_in[5];
    const float* replay_q = (const float*)d_in[6];
    const float* weight   = (const float*)d_in[7];

    const int B   = in_sizes[2];
    const int tau = in_sizes[6] / B;
    const int N   = in_sizes[0] / (tau * B);
    const int T   = in_sizes[4] / B;

    float gamma_T = 1.0f;
    for (int i = 0; i < T; ++i) gamma_T *= GAMMA_F;

    float* out = (float*)d_out;

    cudaMemsetAsync(out, 0, sizeof(float), 0);   // zero loss accumulator

    iqn_td_fused_kernel<<<B / WPB, THREADS>>>(q, next_n_q, action, naction,
                                              reward, done, replay_q, weight,
                                              out, B, N, T, gamma_T);
}

// round 13
// speedup vs baseline: 1.5661x; 1.5661x over previous
#include <cuda_runtime.h>
#include <math.h>

#define GAMMA_F 0.99f
#define TAU 64          // tau == tauP == 64 (fixed for this problem)
#define BMAX 4096
#define TROW (TAU + 4)  // padded smem row for LDS.128 (68 words)

// scratch: gathered chosen-action quantiles + bellman targets, t-major (t*B+b)
__device__ float g_qsa[TAU * BMAX];
__device__ float g_tgt[TAU * BMAX];

__device__ __forceinline__ unsigned long long make_evict_last_policy() {
    unsigned long long pol;
    asm volatile("createpolicy.fractional.L2::evict_last.b64 %0, 1.0;" : "=l"(pol));
    return pol;
}
__device__ __forceinline__ float ldg_el(const float* p, unsigned long long pol) {
    float v;
    asm volatile("ld.global.nc.L2::cache_hint.f32 %0, [%1], %2;"
                 : "=f"(v) : "l"(p), "l"(pol));
    return v;
}

// K1: pure gather, no barriers. warp = one tau, lanes = 32 consecutive b
// (page-local: one LDG touches ONE 2MB page). Stores drain via scoreboard.
__global__ void __launch_bounds__(256)
iqn_gather_kernel(const float* __restrict__ q,          // (tau, B, N)
                  const float* __restrict__ next_n_q,   // (tauP, B, N)
                  const int*   __restrict__ action,     // (B,)
                  const int*   __restrict__ next_action,// (B,)
                  const float* __restrict__ reward,     // (T, B)
                  const int*   __restrict__ done,       // (B,)
                  int B, int N, int T, float gamma_T)
{
    const int lane = threadIdx.x & 31;
    const int w    = threadIdx.x >> 5;
    const int b    = blockIdx.x * 32 + lane;
    const int t    = blockIdx.y * 8 + w;

    const int a  = action[b];        // coalesced
    const int an = next_action[b];
    float r_sum = 0.0f, g = 1.0f;
    #pragma unroll 4
    for (int tt = 0; tt < T; ++tt) {
        r_sum = fmaf(g, reward[tt * B + b], r_sum);
        g *= GAMMA_F;
    }
    const float coef = (done[b] != 0) ? 0.0f : gamma_T;

    const unsigned long long pol = make_evict_last_policy();
    const size_t base = (size_t)t * (size_t)B * (size_t)N + (size_t)b * (size_t)N;

    g_qsa[t * B + b] = ldg_el(q + base + a, pol);                         // coalesced STG
    g_tgt[t * B + b] = fmaf(coef, ldg_el(next_n_q + base + an, pol), r_sum);
}

// K2: all-coalesced compute. block = 8 b x 64 t (512 thr), tid = t*8 + bl.
// targets staged to padded smem rows -> LDS.128 broadcast in the pair loop.
__global__ void __launch_bounds__(512)
iqn_compute_kernel(const float* __restrict__ replay_q,  // (tau, B)
                   const float* __restrict__ weight,    // (B,)
                   float* __restrict__ out,             // out[0]=loss, out[1..B]=td
                   int B)
{
    const int tid  = threadIdx.x;
    const int lane = tid & 31;
    const int w    = tid >> 5;            // 16 warps; warp w covers t = 4w..4w+3
    const int bl   = tid & 7;
    const int t    = tid >> 3;
    const int b0   = blockIdx.x * 8;
    const int b    = b0 + bl;

    __shared__ __align__(16) float s_tgt[8][TROW];
    __shared__ float s_red[16][8];

    // coalesced loads (t-major layout matches tid order)
    const float qsa = g_qsa[t * B + b];
    const float tgt = g_tgt[t * B + b];
    const float rq  = replay_q[t * B + b];
    const float rq1 = 1.0f - rq;

    s_tgt[bl][t] = tgt;                   // <=2-way conflict STS, once
    __syncthreads();

    // pair loop over 64 tp via LDS.128 rows (bank-verified conflict-free)
    const float4* __restrict__ trow = (const float4*)&s_tgt[bl][0];
    float acce = 0.0f, acco = 0.0f;
    #pragma unroll
    for (int j4 = 0; j4 < TAU / 4; ++j4) {
        const float4 t4 = trow[j4];
        // kappa=1: c=min(|u|,1); h=c*(0.5c-1)+|u|; f=(u<0)?(1-rq):rq
        {   const float u = t4.x - qsa, au = fabsf(u), c = fminf(au, 1.0f);
            acce = fmaf((u < 0.0f) ? rq1 : rq, fmaf(c, fmaf(0.5f, c, -1.0f), au), acce); }
        {   const float u = t4.y - qsa, au = fabsf(u), c = fminf(au, 1.0f);
            acco = fmaf((u < 0.0f) ? rq1 : rq, fmaf(c, fmaf(0.5f, c, -1.0f), au), acco); }
        {   const float u = t4.z - qsa, au = fabsf(u), c = fminf(au, 1.0f);
            acce = fmaf((u < 0.0f) ? rq1 : rq, fmaf(c, fmaf(0.5f, c, -1.0f), au), acce); }
        {   const float u = t4.w - qsa, au = fabsf(u), c = fminf(au, 1.0f);
            acco = fmaf((u < 0.0f) ? rq1 : rq, fmaf(c, fmaf(0.5f, c, -1.0f), au), acco); }
    }

    // reduce over t (64 per b): warp holds 4 t x 8 bl
    float part = acce + acco;
    part += __shfl_down_sync(0xffffffffu, part, 16);
    part += __shfl_down_sync(0xffffffffu, part, 8);
    if (lane < 8) s_red[w][lane] = part;
    __syncthreads();

    if (tid < 8) {
        float tot = 0.0f;
        #pragma unroll
        for (int k = 0; k < 16; ++k)
            tot += s_red[k][tid];
        const float td = tot * (1.0f / (float)TAU);   // mean over tauP
        out[1 + b0 + tid] = td;
        float wsum = td * weight[b0 + tid];
        wsum += __shfl_down_sync(0x000000ffu, wsum, 4);
        wsum += __shfl_down_sync(0x000000ffu, wsum, 2);
        wsum += __shfl_down_sync(0x000000ffu, wsum, 1);
        if (tid == 0)
            atomicAdd(out, wsum * (1.0f / (float)B)); // one atomic per CTA
    }
}

extern "C" void kernel_launch(void* const* d_in, const int* in_sizes, int n_in,
                              void* d_out, int out_size)
{
    const float* q        = (const float*)d_in[0];
    const float* next_n_q = (const float*)d_in[1];
    const int*   action   = (const int*)  d_in[2];
    const int*   naction  = (const int*)  d_in[3];
    const float* reward   = (const float*)d_in[4];
    const int*   done     = (const int*)  d_in[5];
    const float* replay_q = (const float*)d_in[6];
    const float* weight   = (const float*)d_in[7];

    const int B   = in_sizes[2];
    const int tau = in_sizes[6] / B;
    const int N   = in_sizes[0] / (tau * B);
    const int T   = in_sizes[4] / B;

    float gamma_T = 1.0f;
    for (int i = 0; i < T; ++i) gamma_T *= GAMMA_F;

    float* out = (float*)d_out;

    cudaMemsetAsync(out, 0, sizeof(float), 0);   // zero loss accumulator

    dim3 g1(B / 32, tau / 8);
    iqn_gather_kernel<<<g1, 256>>>(q, next_n_q, action, naction, reward, done,
                                   B, N, T, gamma_T);
    iqn_compute_kernel<<<B / 8, 512>>>(replay_q, weight, out, B);
}

// round 14
// speedup vs baseline: 1.7889x; 1.1422x over previous
#include <cuda_runtime.h>
#include <math.h>

#define GAMMA_F 0.99f
#define TAU 64          // tau == tauP == 64
#define BPB 16          // batch elements per block
#define THREADS 256     // 8 warps; grid = B/16 = 256
#define NW (THREADS / 32)
#define TPT 4           // taus per thread in compute (4 acc chains)
#define TROW (TAU + 4)  // padded target row (68 words): rows 4 banks apart

__device__ __forceinline__ unsigned long long make_evict_last_policy() {
    unsigned long long pol;
    asm volatile("createpolicy.fractional.L2::evict_last.b64 %0, 1.0;" : "=l"(pol));
    return pol;
}
__device__ __forceinline__ float ldg_el(const float* p, unsigned long long pol) {
    float v;
    asm volatile("ld.global.nc.L2::cache_hint.f32 %0, [%1], %2;"
                 : "=f"(v) : "l"(p), "l"(pol));
    return v;
}

// Fused kernel. Gather: lane=(ts,bl) covers 2 taus x 16 b (page-local).
// Compute: thread = (b = tid&15, 4 consecutive taus) -> 4 independent FMA
// chains fed by ONE LDS.128 target read per 4 tp (16 pair-ops per LDS).
__global__ void __launch_bounds__(THREADS)
iqn_td_fused_kernel(const float* __restrict__ q,          // (tau, B, N)
                    const float* __restrict__ next_n_q,   // (tauP, B, N)
                    const int*   __restrict__ action,     // (B,)
                    const int*   __restrict__ next_action,// (B,)
                    const float* __restrict__ reward,     // (T, B)
                    const int*   __restrict__ done,       // (B,)
                    const float* __restrict__ replay_q,   // (tau, B)
                    const float* __restrict__ weight,     // (B,)
                    float* __restrict__ out,              // out[0]=loss, out[1..B]=td
                    int B, int N, int T, float gamma_T)
{
    const int tid  = threadIdx.x;
    const int lane = tid & 31;
    const int w    = tid >> 5;              // warp 0..7
    const int b0   = blockIdx.x * BPB;

    __shared__ float s_qsa[TAU][BPB];                 // [t][b]
    __shared__ __align__(16) float s_tgt[BPB][TROW];  // [b][tp], padded
    __shared__ int   s_a[BPB], s_an[BPB];
    __shared__ float s_rsum[BPB], s_coef[BPB];
    __shared__ float s_red[BPB][BPB];                 // [t-group][b]

    // ---- prelude: per-b scalars ----
    if (tid < BPB) {
        const int b = b0 + tid;
        s_a[tid]  = action[b];
        s_an[tid] = next_action[b];
        float r_sum = 0.0f, g = 1.0f;
        for (int tt = 0; tt < T; ++tt) {
            r_sum = fmaf(g, reward[tt * B + b], r_sum);
            g *= GAMMA_F;
        }
        s_rsum[tid] = r_sum;
        s_coef[tid] = (done[b] != 0) ? 0.0f : gamma_T;
    }
    __syncthreads();

    // ---- gather: lane = (ts = lane>>4, bl = lane&15); 4 passes ----
    {
        const unsigned long long pol = make_evict_last_policy();
        const int bl = lane & 15;
        const int ts = lane >> 4;           // 0..1
        const int   a    = s_a[bl];
        const int   an   = s_an[bl];
        const float rsum = s_rsum[bl];
        const float coef = s_coef[bl];
        const size_t plane = (size_t)B * (size_t)N;
        const size_t rowb  = (size_t)(b0 + bl) * (size_t)N;

        #pragma unroll
        for (int k = 0; k < 4; ++k) {       // taus: k*16 + w*2 + ts
            const int t = k * 16 + w * 2 + ts;
            const size_t base = (size_t)t * plane + rowb;
            s_qsa[t][bl] = ldg_el(q + base + a, pol);
            s_tgt[bl][t] = fmaf(coef, ldg_el(next_n_q + base + an, pol), rsum);
        }
    }
    __syncthreads();

    // ---- compute: thread = (bl = tid&15, taus = (tid>>4)*4 .. +3) ----
    const int bl = tid & 15;
    const int tg = tid >> 4;                // 0..15
    const int tb = tg * TPT;

    float qsa[TPT], rq[TPT], rq1[TPT], acc[TPT];
    #pragma unroll
    for (int j = 0; j < TPT; ++j) {
        qsa[j] = s_qsa[tb + j][bl];
        rq[j]  = replay_q[(tb + j) * B + b0 + bl];   // coalesced, L2-hot
        rq1[j] = 1.0f - rq[j];
        acc[j] = 0.0f;
    }

    // pair loop: ONE LDS.128 -> 16 pair computations (4 tgt x 4 chains)
    // kappa=1: c=min(|u|,1); h = c*(0.5c-1)+|u|; f = (u<0)?(1-rq):rq
    const float4* __restrict__ trow = (const float4*)&s_tgt[bl][0];
    #pragma unroll
    for (int j4 = 0; j4 < TAU / 4; ++j4) {
        const float4 t4 = trow[j4];
        #pragma unroll
        for (int j = 0; j < TPT; ++j) {
            {   const float u = t4.x - qsa[j], au = fabsf(u), c = fminf(au, 1.0f);
                acc[j] = fmaf((u < 0.0f) ? rq1[j] : rq[j],
                              fmaf(c, fmaf(0.5f, c, -1.0f), au), acc[j]); }
            {   const float u = t4.y - qsa[j], au = fabsf(u), c = fminf(au, 1.0f);
                acc[j] = fmaf((u < 0.0f) ? rq1[j] : rq[j],
                              fmaf(c, fmaf(0.5f, c, -1.0f), au), acc[j]); }
            {   const float u = t4.z - qsa[j], au = fabsf(u), c = fminf(au, 1.0f);
                acc[j] = fmaf((u < 0.0f) ? rq1[j] : rq[j],
                              fmaf(c, fmaf(0.5f, c, -1.0f), au), acc[j]); }
            {   const float u = t4.w - qsa[j], au = fabsf(u), c = fminf(au, 1.0f);
                acc[j] = fmaf((u < 0.0f) ? rq1[j] : rq[j],
                              fmaf(c, fmaf(0.5f, c, -1.0f), au), acc[j]); }
        }
    }

    // ---- reduce: 16 tau-groups per b ----
    s_red[tg][bl] = (acc[0] + acc[1]) + (acc[2] + acc[3]);
    __syncthreads();

    if (tid < BPB) {
        const int b = b0 + tid;
        float tot = 0.0f;
        #pragma unroll
        for (int k = 0; k < BPB; ++k)
            tot += s_red[k][tid];
        const float td = tot * (1.0f / (float)TAU);   // mean over tauP
        out[1 + b] = td;
        float wsum = td * weight[b];
        wsum += __shfl_down_sync(0x0000ffffu, wsum, 8);
        wsum += __shfl_down_sync(0x0000ffffu, wsum, 4);
        wsum += __shfl_down_sync(0x0000ffffu, wsum, 2);
        wsum += __shfl_down_sync(0x0000ffffu, wsum, 1);
        if (tid == 0)
            atomicAdd(out, wsum * (1.0f / (float)B)); // one atomic per CTA
    }
}

extern "C" void kernel_launch(void* const* d_in, const int* in_sizes, int n_in,
                              void* d_out, int out_size)
{
    const float* q        = (const float*)d_in[0];
    const float* next_n_q = (const float*)d_in[1];
    const int*   action   = (const int*)  d_in[2];
    const int*   naction  = (const int*)  d_in[3];
    const float* reward   = (const float*)d_in[4];
    const int*   done     = (const int*)  d_in[5];
    const float* replay_q = (const float*)d_in[6];
    const float* weight   = (const float*)d_in[7];

    const int B   = in_sizes[2];
    const int tau = in_sizes[6] / B;
    const int N   = in_sizes[0] / (tau * B);
    const int T   = in_sizes[4] / B;

    float gamma_T = 1.0f;
    for (int i = 0; i < T; ++i) gamma_T *= GAMMA_F;

    float* out = (float*)d_out;

    cudaMemsetAsync(out, 0, sizeof(float), 0);   // zero loss accumulator

    iqn_td_fused_kernel<<<B / BPB, THREADS>>>(q, next_n_q, action, naction,
                                              reward, done, replay_q, weight,
                                              out, B, N, T, gamma_T);
}

// round 15
// speedup vs baseline: 2.0641x; 1.1538x over previous
#include <cuda_runtime.h>
#include <math.h>

#define GAMMA_F 0.99f
#define TAU 64          // tau == tauP == 64 (fixed)
#define BPB 8           // batch elements per block (= warps per block)
#define THREADS 256
#define FULL 0xffffffffu

__device__ __forceinline__ unsigned long long make_evict_last_policy() {
    unsigned long long pol;
    asm volatile("createpolicy.fractional.L2::evict_last.b64 %0, 1.0;" : "=l"(pol));
    return pol;
}
__device__ __forceinline__ float ldg_el(const float* p, unsigned long long pol) {
    float v;
    asm volatile("ld.global.nc.L2::cache_hint.f32 %0, [%1], %2;"
                 : "=f"(v) : "l"(p), "l"(pol));
    return v;
}

// count of elements < v in sorted s[0..63]
__device__ __forceinline__ int lbound64(const float* __restrict__ s, float v) {
    int pos = 0;
    #pragma unroll
    for (int st = 64; st >= 1; st >>= 1) {
        const int np = pos + st;
        if (np <= 64 && s[np - 1] < v) pos = np;
    }
    return pos;
}

// O(tau log tau) algorithm: per b, sort the 64 bellman targets, prefix-sum
// (E1=Σtgt, E2=Σtgt²), then each current-quantile t evaluates its whole
// Σ_tp f·h in closed form from 3 binary searches (regions split at x-1,x,x+1).
__global__ void __launch_bounds__(THREADS)
iqn_td_fused_kernel(const float* __restrict__ q,          // (tau, B, N)
                    const float* __restrict__ next_n_q,   // (tauP, B, N)
                    const int*   __restrict__ action,     // (B,)
                    const int*   __restrict__ next_action,// (B,)
                    const float* __restrict__ reward,     // (T, B)
                    const int*   __restrict__ done,       // (B,)
                    const float* __restrict__ replay_q,   // (tau, B)
                    const float* __restrict__ weight,     // (B,)
                    float* __restrict__ out,              // out[0]=loss, out[1..B]=td
                    int B, int N, int T, float gamma_T)
{
    const int tid  = threadIdx.x;
    const int lane = tid & 31;
    const int w    = tid >> 5;              // warp -> owns b0 + w in compute
    const int b0   = blockIdx.x * BPB;

    __shared__ float s_qsa[BPB][TAU];       // [b][t]
    __shared__ float s_rq [BPB][TAU];
    __shared__ float s_srt[BPB][TAU];       // sorted targets
    __shared__ float s_E1 [BPB][TAU + 1];   // exclusive prefix sums
    __shared__ float s_E2 [BPB][TAU + 1];
    __shared__ int   s_a[BPB], s_an[BPB];
    __shared__ float s_rsum[BPB], s_coef[BPB];
    __shared__ float s_wsum[BPB];

    // ---- prelude: per-b scalars ----
    if (tid < BPB) {
        const int b = b0 + tid;
        s_a[tid]  = action[b];
        s_an[tid] = next_action[b];
        float r_sum = 0.0f, g = 1.0f;
        for (int tt = 0; tt < T; ++tt) {
            r_sum = fmaf(g, reward[tt * B + b], r_sum);
            g *= GAMMA_F;
        }
        s_rsum[tid] = r_sum;
        s_coef[tid] = (done[b] != 0) ? 0.0f : gamma_T;
    }
    __syncthreads();

    // ---- gather (page-local, R6-proven mapping + evict_last) ----
    {
        const unsigned long long pol = make_evict_last_policy();
        const int bl = lane & 7;
        const int ts = lane >> 3;            // 0..3
        const int   a    = s_a[bl];
        const int   an   = s_an[bl];
        const float rsum = s_rsum[bl];
        const float coef = s_coef[bl];
        const size_t plane = (size_t)B * (size_t)N;
        const size_t rowb  = (size_t)(b0 + bl) * (size_t)N;

        #pragma unroll
        for (int k = 0; k < 2; ++k) {        // t = k*32 + w*4 + ts
            const int t = k * 32 + w * 4 + ts;
            const size_t base = (size_t)t * plane + rowb;
            s_qsa[bl][t] = ldg_el(q + base + a, pol);
            s_srt[bl][t] = fmaf(coef, ldg_el(next_n_q + base + an, pol), rsum);
            s_rq [bl][t] = replay_q[t * B + b0 + bl];
        }
    }
    __syncthreads();

    // ================= warp w processes b = b0 + w =================
    float* __restrict__ srt = s_srt[w];
    float* __restrict__ e1  = s_E1[w];
    float* __restrict__ e2  = s_E2[w];

    // ---- bitonic sort of 64 targets, in registers via shfl ----
    // element i = lane + 32*r lives in reg r (r0, r1)
    float r0 = srt[lane];
    float r1 = srt[lane + 32];

    #pragma unroll
    for (int k = 2; k <= 32; k <<= 1) {
        #pragma unroll
        for (int j = 16; j >= 1; j >>= 1) {
            if (j >= k) continue;            // j runs k/2 .. 1
            const float vp0 = __shfl_xor_sync(FULL, r0, j);
            const float vp1 = __shfl_xor_sync(FULL, r1, j);
            const bool lower = ((lane & j) == 0);
            const bool up0 = ((lane & k) == 0);
            const bool up1 = (((lane + 32) & k) == 0);
            r0 = (up0 == lower) ? fminf(r0, vp0) : fmaxf(r0, vp0);
            r1 = (up1 == lower) ? fminf(r1, vp1) : fmaxf(r1, vp1);
        }
    }
    // k = 64 merge: j=32 is the intra-lane exchange (up = true everywhere)
    {
        const float lo = fminf(r0, r1), hi = fmaxf(r0, r1);
        r0 = lo; r1 = hi;
        #pragma unroll
        for (int j = 16; j >= 1; j >>= 1) {
            const float vp0 = __shfl_xor_sync(FULL, r0, j);
            const float vp1 = __shfl_xor_sync(FULL, r1, j);
            const bool lower = ((lane & j) == 0);
            r0 = lower ? fminf(r0, vp0) : fmaxf(r0, vp0);
            r1 = lower ? fminf(r1, vp1) : fmaxf(r1, vp1);
        }
    }
    srt[lane]      = r0;                     // sorted ascending
    srt[lane + 32] = r1;

    // ---- prefix sums: E1[i]=Σ_{<i} tgt, E2[i]=Σ_{<i} tgt² ----
    float p0 = r0, p1 = r1, q0 = r0 * r0, q1 = r1 * r1;
    #pragma unroll
    for (int off = 1; off < 32; off <<= 1) {
        const float a0 = __shfl_up_sync(FULL, p0, off);
        const float a1 = __shfl_up_sync(FULL, p1, off);
        const float c0 = __shfl_up_sync(FULL, q0, off);
        const float c1 = __shfl_up_sync(FULL, q1, off);
        if (lane >= off) { p0 += a0; p1 += a1; q0 += c0; q1 += c1; }
    }
    const float tot0  = __shfl_sync(FULL, p0, 31);
    const float tot0q = __shfl_sync(FULL, q0, 31);
    if (lane == 0) { e1[0] = 0.0f; e2[0] = 0.0f; }
    e1[lane + 1]  = p0;          e2[lane + 1]  = q0;
    e1[lane + 33] = tot0 + p1;   e2[lane + 33] = tot0q + q1;
    __syncwarp();

    // ---- closed-form evaluation for t = lane and t = lane+32 ----
    float acc = 0.0f;
    #pragma unroll
    for (int kk = 0; kk < 2; ++kk) {
        const int   t   = lane + kk * 32;
        const float x   = s_qsa[w][t];
        const float rq  = s_rq[w][t];
        const float rqm = 1.0f - rq;
        const int k1 = lbound64(srt, x - 1.0f);  // region A: tgt < x-1
        const int k2 = lbound64(srt, x);         // region B: [x-1, x)
        const int k3 = lbound64(srt, x + 1.0f);  // region C: [x, x+1)

        const float e1a = e1[k1], e1b = e1[k2], e1c = e1[k3], e1d = e1[TAU];
        const float e2a = e2[k1], e2b = e2[k2], e2c = e2[k3];
        const float x2 = x * x;
        // A: f=(1-rq), h = x - tgt - 0.5
        const float vA = rqm * ((float)k1 * (x - 0.5f) - e1a);
        // B: f=(1-rq), h = 0.5 (tgt-x)^2
        const float vB = rqm * 0.5f *
            ((e2b - e2a) - 2.0f * x * (e1b - e1a) + (float)(k2 - k1) * x2);
        // C: f=rq, h = 0.5 (tgt-x)^2
        const float vC = rq * 0.5f *
            ((e2c - e2b) - 2.0f * x * (e1c - e1b) + (float)(k3 - k2) * x2);
        // D: f=rq, h = tgt - x - 0.5
        const float vD = rq * ((e1d - e1c) - (float)(TAU - k3) * (x + 0.5f));
        acc += (vA + vB) + (vC + vD);
    }

    // ---- warp reduce over t; finalize b ----
    #pragma unroll
    for (int off = 16; off > 0; off >>= 1)
        acc += __shfl_down_sync(FULL, acc, off);
    if (lane == 0) {
        const float td = acc * (1.0f / (float)TAU);   // mean over tauP
        out[1 + b0 + w] = td;
        s_wsum[w] = td * weight[b0 + w];
    }
    __syncthreads();

    if (tid < BPB) {
        float v = s_wsum[tid];
        v += __shfl_down_sync(0x000000ffu, v, 4);
        v += __shfl_down_sync(0x000000ffu, v, 2);
        v += __shfl_down_sync(0x000000ffu, v, 1);
        if (tid == 0)
            atomicAdd(out, v * (1.0f / (float)B));    // one atomic per CTA
    }
}

extern "C" void kernel_launch(void* const* d_in, const int* in_sizes, int n_in,
                              void* d_out, int out_size)
{
    const float* q        = (const float*)d_in[0];
    const float* next_n_q = (const float*)d_in[1];
    const int*   action   = (const int*)  d_in[2];
    const int*   naction  = (const int*)  d_in[3];
    const float* reward   = (const float*)d_in[4];
    const int*   done     = (const int*)  d_in[5];
    const float* replay_q = (const float*)d_in[6];
    const float* weight   = (const float*)d_in[7];

    const int B   = in_sizes[2];
    const int tau = in_sizes[6] / B;
    const int N   = in_sizes[0] / (tau * B);
    const int T   = in_sizes[4] / B;

    float gamma_T = 1.0f;
    for (int i = 0; i < T; ++i) gamma_T *= GAMMA_F;

    float* out = (float*)d_out;

    cudaMemsetAsync(out, 0, sizeof(float), 0);   // zero loss accumulator

    iqn_td_fused_kernel<<<B / BPB, THREADS>>>(q, next_n_q, action, naction,
                                              reward, done, replay_q, weight,
                                              out, B, N, T, gamma_T);
}